// round 7
// baseline (speedup 1.0000x reference)
#include <cuda_runtime.h>

// LSTM_60808146977081: B=4096, T=512, I=10, H=32, fp32.
// One warp per batch; lane = hidden unit; weights register-resident.
// R6: deep x prefetch (L2 prefetch t+8 + register prefetch t+1) to hide the
// 577-cyc DRAM / 234-cyc L2 latency of the 40B/step x stream, and log2e
// folded into gate weights so every activation is the uniform chain
// ex2 -> add -> rcp [-> fma], cutting the per-step serial tail.

#define FULL_MASK 0xFFFFFFFFu

__device__ __forceinline__ float2 ffma2(float2 a, float2 b, float2 c) {
    union F2U { float2 f; unsigned long long u; };
    F2U ua, ub, uc, ud;
    ua.f = a; ub.f = b; uc.f = c;
    asm("fma.rn.f32x2 %0, %1, %2, %3;"
        : "=l"(ud.u) : "l"(ua.u), "l"(ub.u), "l"(uc.u));
    return ud.f;
}

__device__ __forceinline__ float ex2_approx(float x) {
    float r;
    asm("ex2.approx.f32 %0, %1;" : "=f"(r) : "f"(x));
    return r;
}
__device__ __forceinline__ float rcp_approx(float x) {
    float r;
    asm("rcp.approx.f32 %0, %1;" : "=f"(r) : "f"(x));
    return r;
}

// Gate pre-activations arrive PRE-SCALED:
//   i,f,o rows scaled by -log2(e)      -> sigmoid(raw) = rcp(1 + ex2(y))
//   g   rows scaled by -2*log2(e)      -> tanh(raw)    = 2*rcp(1+ex2(y)) - 1
// ex2 -> inf => rcp -> 0 (sig 0 / tanh -1); ex2 -> 0 => rcp(1)=1 (sig 1 / tanh +1).
__device__ __forceinline__ float sig_pre(float y) {
    return rcp_approx(1.0f + ex2_approx(y));
}
__device__ __forceinline__ float tanh_pre(float y) {
    return fmaf(2.0f, rcp_approx(1.0f + ex2_approx(y)), -1.0f);
}

__global__ void __launch_bounds__(128, 2)
lstm_r6(const float* __restrict__ x,
        const float* __restrict__ h0,
        const float* __restrict__ c0,
        const float* __restrict__ W_ih,
        const float* __restrict__ W_hh,
        const float* __restrict__ b_ih,
        const float* __restrict__ b_hh,
        const float* __restrict__ W_lin,
        const float* __restrict__ b_lin,
        float* __restrict__ out)
{
    constexpr int T = 512;
    constexpr int I = 10;
    constexpr float L2E  = 1.44269504088896340736f;   // log2(e)
    // per-gate fold factors: i, f, g, o
    const float gscale[4] = { -L2E, -L2E, -2.0f * L2E, -L2E };

    const int warp = threadIdx.x >> 5;
    const int lane = threadIdx.x & 31;
    const int b    = blockIdx.x * 4 + warp;

    __shared__ float sh[4][2][32];   // per-warp h broadcast, double-buffered

    // ---- Weights -> registers, pre-scaled by gate fold factor ----
    float2 wh[4][16];   // W_hh rows (gate g*32+lane), pairs along j
    float2 wi[4][5];    // W_ih rows, pairs along i
    float  bias[4];
#pragma unroll
    for (int g = 0; g < 4; g++) {
        const float s = gscale[g];
        const int r = g * 32 + lane;
        const float2* whp = reinterpret_cast<const float2*>(W_hh + r * 32);
#pragma unroll
        for (int p = 0; p < 16; p++) {
            float2 w = whp[p];
            wh[g][p] = make_float2(w.x * s, w.y * s);
        }
        const float2* wip = reinterpret_cast<const float2*>(W_ih + r * I);
#pragma unroll
        for (int q = 0; q < 5; q++) {
            float2 w = wip[q];
            wi[g][q] = make_float2(w.x * s, w.y * s);
        }
        bias[g] = (b_ih[r] + b_hh[r]) * s;
    }
    const float wl = W_lin[lane];

    float h = h0[b * 32 + lane];
    float c = c0[b * 32 + lane];

    const float* xrow = x + (size_t)b * (T * I);
    const float2* xw  = reinterpret_cast<const float2*>(xrow);

    // Warm the L2 for the first few steps, then load step 0 into regs.
#pragma unroll
    for (int pf = 0; pf < 8; pf++)
        asm volatile("prefetch.global.L2 [%0];" :: "l"(xrow + pf * I));
    float2 xc[5], xn[5];
#pragma unroll
    for (int q = 0; q < 5; q++) xc[q] = xw[q];

#pragma unroll 2
    for (int t = 0; t < T; t++) {
        const int buf = t & 1;
        sh[warp][buf][lane] = h;
        __syncwarp();

        // Deep prefetch: pull x(t+8) toward L2 (hides DRAM 577cyc; free of regs)
        {
            const int tp = (t + 8 < T) ? t + 8 : T - 1;
            asm volatile("prefetch.global.L2 [%0];" :: "l"(xrow + tp * I));
        }
        // Register prefetch: x(t+1) (hides L2-hit 234cyc behind this step's FMAs)
        {
            const float2* nxt = xw + (size_t)((t + 1 < T) ? t + 1 : t) * 5;
#pragma unroll
            for (int q = 0; q < 5; q++) xn[q] = nxt[q];
        }

        float2 acc[4];
#pragma unroll
        for (int g = 0; g < 4; g++) acc[g] = make_float2(bias[g], 0.0f);

        // Recurrent matvec: h broadcast from smem, 4 independent FFMA2 chains
        const float4* hp4 = reinterpret_cast<const float4*>(sh[warp][buf]);
#pragma unroll
        for (int p = 0; p < 8; p++) {
            const float4 hv = hp4[p];
            const float2 ha = make_float2(hv.x, hv.y);
            const float2 hb = make_float2(hv.z, hv.w);
#pragma unroll
            for (int g = 0; g < 4; g++) {
                acc[g] = ffma2(wh[g][2 * p],     ha, acc[g]);
                acc[g] = ffma2(wh[g][2 * p + 1], hb, acc[g]);
            }
        }
        // Input matvec
#pragma unroll
        for (int q = 0; q < 5; q++) {
#pragma unroll
            for (int g = 0; g < 4; g++)
                acc[g] = ffma2(wi[g][q], xc[q], acc[g]);
        }

        // Uniform activations on pre-scaled gates
        const float yi = acc[0].x + acc[0].y;
        const float yf = acc[1].x + acc[1].y;
        const float yg = acc[2].x + acc[2].y;
        const float yo = acc[3].x + acc[3].y;

        const float ig = sig_pre(yi);
        const float fg = sig_pre(yf);
        const float gc = tanh_pre(yg);
        const float og = sig_pre(yo);

        c = fmaf(fg, c, ig * gc);
        h = og * tanh_pre(-2.0f * L2E * c);

#pragma unroll
        for (int q = 0; q < 5; q++) xc[q] = xn[q];
    }

    // out[b] = sum_k h[k] * W_lin[0,k] + b_lin
    float v = h * wl;
#pragma unroll
    for (int off = 16; off; off >>= 1)
        v += __shfl_xor_sync(FULL_MASK, v, off);
    if (lane == 0) out[b] = v + b_lin[0];
}

extern "C" void kernel_launch(void* const* d_in, const int* in_sizes, int n_in,
                              void* d_out, int out_size)
{
    const float* x     = (const float*)d_in[0];
    const float* h0    = (const float*)d_in[1];
    const float* c0    = (const float*)d_in[2];
    const float* W_ih  = (const float*)d_in[3];
    const float* W_hh  = (const float*)d_in[4];
    const float* b_ih  = (const float*)d_in[5];
    const float* b_hh  = (const float*)d_in[6];
    const float* W_lin = (const float*)d_in[7];
    const float* b_lin = (const float*)d_in[8];
    float* out = (float*)d_out;

    // 4096 batches, 1 per warp, 4 warps per 128-thread block -> 1024 blocks
    lstm_r6<<<1024, 128>>>(x, h0, c0, W_ih, W_hh, b_ih, b_hh,
                           W_lin, b_lin, out);
}

// round 10
// speedup vs baseline: 1.5278x; 1.5278x over previous
#include <cuda_runtime.h>

// LSTM_60808146977081: B=4096, T=512, I=10, H=32, fp32.
// One warp per batch; lane = hidden unit; weights register-resident.
// R7: (1) tanh.approx.f32 activations (sigmoid via 0.5-folded weights) ->
//     5 MUFU ops/step instead of 10 ex2/rcp, much shorter serial tail.
//     (2) input matvec for step t+1 computed during step t's activation
//     phase (independent of h -> fills the MUFU latency window with FMA).
//     (3) 2-step x load pipeline hides DRAM misses without prefetch instrs.

#define FULL_MASK 0xFFFFFFFFu

__device__ __forceinline__ float2 ffma2(float2 a, float2 b, float2 c) {
    union F2U { float2 f; unsigned long long u; };
    F2U ua, ub, uc, ud;
    ua.f = a; ub.f = b; uc.f = c;
    asm("fma.rn.f32x2 %0, %1, %2, %3;"
        : "=l"(ud.u) : "l"(ua.u), "l"(ub.u), "l"(uc.u));
    return ud.f;
}

__device__ __forceinline__ float tanh_hw(float x) {
    float r;
    asm("tanh.approx.f32 %0, %1;" : "=f"(r) : "f"(x));
    return r;
}

__global__ void __launch_bounds__(128, 2)
lstm_r7(const float* __restrict__ x,
        const float* __restrict__ h0,
        const float* __restrict__ c0,
        const float* __restrict__ W_ih,
        const float* __restrict__ W_hh,
        const float* __restrict__ b_ih,
        const float* __restrict__ b_hh,
        const float* __restrict__ W_lin,
        const float* __restrict__ b_lin,
        float* __restrict__ out)
{
    constexpr int T = 512;
    constexpr int I = 10;
    // gate fold: sigmoid(y) = 0.5*tanh(0.5*y)+0.5 -> scale i,f,o rows by 0.5.
    const float gscale[4] = { 0.5f, 0.5f, 1.0f, 0.5f };

    const int warp = threadIdx.x >> 5;
    const int lane = threadIdx.x & 31;
    const int b    = blockIdx.x * 4 + warp;

    __shared__ float sh[4][2][32];   // per-warp h broadcast, double-buffered

    // ---- Weights -> registers, pre-scaled by gate fold factor ----
    float2 wh[4][16];   // W_hh rows (gate g*32+lane), pairs along j
    float2 wi[4][5];    // W_ih rows, pairs along i
    float  bias[4];
#pragma unroll
    for (int g = 0; g < 4; g++) {
        const float s = gscale[g];
        const int r = g * 32 + lane;
        const float2* whp = reinterpret_cast<const float2*>(W_hh + r * 32);
#pragma unroll
        for (int p = 0; p < 16; p++) {
            float2 w = whp[p];
            wh[g][p] = make_float2(w.x * s, w.y * s);
        }
        const float2* wip = reinterpret_cast<const float2*>(W_ih + r * I);
#pragma unroll
        for (int q = 0; q < 5; q++) {
            float2 w = wip[q];
            wi[g][q] = make_float2(w.x * s, w.y * s);
        }
        bias[g] = (b_ih[r] + b_hh[r]) * s;
    }
    const float wl = W_lin[lane];

    float h = h0[b * 32 + lane];
    float c = c0[b * 32 + lane];

    const float2* xw = reinterpret_cast<const float2*>(x + (size_t)b * (T * I));

    // x pipeline: xg = x-gate contribution (incl bias) for step t;
    //             xc = x(t+1) (arrived);  xn = x(t+2) (in flight).
    float2 xc[5], xn[5];
    float2 xg[4];
    {
        float2 x0[5];
#pragma unroll
        for (int q = 0; q < 5; q++) x0[q] = xw[q];            // x(0)
#pragma unroll
        for (int q = 0; q < 5; q++) xc[q] = xw[5 + q];        // x(1)
#pragma unroll
        for (int q = 0; q < 5; q++) xn[q] = xw[10 + q];       // x(2)
#pragma unroll
        for (int g = 0; g < 4; g++) {
            xg[g] = make_float2(bias[g], 0.0f);
#pragma unroll
            for (int q = 0; q < 5; q++) xg[g] = ffma2(wi[g][q], x0[q], xg[g]);
        }
    }

#pragma unroll 2
    for (int t = 0; t < T; t++) {
        const int buf = t & 1;
        sh[warp][buf][lane] = h;
        __syncwarp();

        // ---- Recurrent matvec: acc starts from precomputed x-gates ----
        float2 acc[4];
#pragma unroll
        for (int g = 0; g < 4; g++) acc[g] = xg[g];

        const float4* hp4 = reinterpret_cast<const float4*>(sh[warp][buf]);
#pragma unroll
        for (int p = 0; p < 8; p++) {
            const float4 hv = hp4[p];
            const float2 ha = make_float2(hv.x, hv.y);
            const float2 hb = make_float2(hv.z, hv.w);
#pragma unroll
            for (int g = 0; g < 4; g++) {
                acc[g] = ffma2(wh[g][2 * p],     ha, acc[g]);
                acc[g] = ffma2(wh[g][2 * p + 1], hb, acc[g]);
            }
        }

        const float yi = acc[0].x + acc[0].y;
        const float yf = acc[1].x + acc[1].y;
        const float yg = acc[2].x + acc[2].y;
        const float yo = acc[3].x + acc[3].y;

        // MUFU issues (latency ~16, rt 8 shared) ...
        const float ti = tanh_hw(yi);
        const float tf = tanh_hw(yf);
        const float gc = tanh_hw(yg);
        const float to = tanh_hw(yo);

        // ... overlapped with INDEPENDENT work: x-gates for step t+1
        // (xc = x(t+1) arrived >1 step ago) + advance the load pipeline.
#pragma unroll
        for (int g = 0; g < 4; g++) {
            xg[g] = make_float2(bias[g], 0.0f);
#pragma unroll
            for (int q = 0; q < 5; q++) xg[g] = ffma2(wi[g][q], xc[q], xg[g]);
        }
#pragma unroll
        for (int q = 0; q < 5; q++) xc[q] = xn[q];
        {
            const int tn = (t + 3 < T) ? t + 3 : T - 1;
            const float2* nxt = xw + (size_t)tn * 5;
#pragma unroll
            for (int q = 0; q < 5; q++) xn[q] = nxt[q];
        }

        // consume tanh results
        const float ig = fmaf(0.5f, ti, 0.5f);
        const float fg = fmaf(0.5f, tf, 0.5f);
        const float og = fmaf(0.5f, to, 0.5f);

        c = fmaf(fg, c, ig * gc);
        h = og * tanh_hw(c);
    }

    // out[b] = sum_k h[k] * W_lin[0,k] + b_lin
    float v = h * wl;
#pragma unroll
    for (int off = 16; off; off >>= 1)
        v += __shfl_xor_sync(FULL_MASK, v, off);
    if (lane == 0) out[b] = v + b_lin[0];
}

extern "C" void kernel_launch(void* const* d_in, const int* in_sizes, int n_in,
                              void* d_out, int out_size)
{
    const float* x     = (const float*)d_in[0];
    const float* h0    = (const float*)d_in[1];
    const float* c0    = (const float*)d_in[2];
    const float* W_ih  = (const float*)d_in[3];
    const float* W_hh  = (const float*)d_in[4];
    const float* b_ih  = (const float*)d_in[5];
    const float* b_hh  = (const float*)d_in[6];
    const float* W_lin = (const float*)d_in[7];
    const float* b_lin = (const float*)d_in[8];
    float* out = (float*)d_out;

    // 4096 batches, 1 per warp, 4 warps per 128-thread block -> 1024 blocks
    lstm_r7<<<1024, 128>>>(x, h0, c0, W_ih, W_hh, b_ih, b_hh,
                           W_lin, b_lin, out);
}